// round 4
// baseline (speedup 1.0000x reference)
#include <cuda_runtime.h>
#include <cstdint>

constexpr int NL  = 6;
constexpr int NH  = 16;
constexpr int DM  = 1024;
constexpr int DH  = 64;
constexpr int DFF = 4096;
constexpr int NV  = 32000;
constexpr int NB  = 2;
constexpr int NS  = 1024;
constexpr int NT  = NB * NS;

__device__ float g_x  [NT * DM];
__device__ float g_res[NT * DM];
__device__ float g_qkv[3 * NT * DM];
__device__ float g_o  [NT * DM];
__device__ float g_ffn[NT * DFF];
__device__ float g_vt [NB * NH * DH * NS];
__device__ float g_sc [(long)NB * NH * NS * NS];
__device__ float g_bt [(long)NV * DM];           // transposed-weight scratch

__device__ __forceinline__ unsigned f2tf(float f) {
    unsigned u;
    asm("cvt.rna.tf32.f32 %0, %1;" : "=r"(u) : "f"(f));
    return u;
}
__device__ __forceinline__ void mma8(float* c, const uint4& a, unsigned b0, unsigned b1) {
    asm volatile(
        "mma.sync.aligned.m16n8k8.row.col.f32.tf32.tf32.f32 "
        "{%0,%1,%2,%3}, {%4,%5,%6,%7}, {%8,%9}, {%0,%1,%2,%3};"
        : "+f"(c[0]), "+f"(c[1]), "+f"(c[2]), "+f"(c[3])
        : "r"(a.x), "r"(a.y), "r"(a.z), "r"(a.w), "r"(b0), "r"(b1));
}
__device__ __forceinline__ uint4 ldm4(unsigned addr) {
    uint4 r;
    asm volatile("ldmatrix.sync.aligned.m8n8.x4.shared.b16 {%0,%1,%2,%3}, [%4];"
                 : "=r"(r.x), "=r"(r.y), "=r"(r.z), "=r"(r.w) : "r"(addr));
    return r;
}

// ---------------------------------------------------------------------------
// Transpose: in (per z: [K][N], row stride ldin) -> out[(z*N+n)*K + k]
// ---------------------------------------------------------------------------
__global__ void __launch_bounds__(256)
tr32(const float* __restrict__ in, float* __restrict__ out,
     int K, int N, int ldin, int zdiv, long sZb, long sZh)
{
    __shared__ float t[32][33];
    const int z = blockIdx.z, zb = z / zdiv, zh = z % zdiv;
    in += zb * sZb + zh * sZh;
    const int k0 = blockIdx.x * 32, n0 = blockIdx.y * 32;
    const int tx = threadIdx.x & 31, ty = threadIdx.x >> 5;
    #pragma unroll
    for (int r = 0; r < 32; r += 8)
        t[ty + r][tx] = in[(long)(k0 + ty + r) * ldin + n0 + tx];
    __syncthreads();
    #pragma unroll
    for (int r = 0; r < 32; r += 8)
        out[((long)z * N + n0 + ty + r) * K + k0 + tx] = t[tx][ty + r];
}

// ---------------------------------------------------------------------------
// tf32 TC GEMM, ldmatrix both operands. BM=128, BK=16, BN in {128,64}.
// A fp32 [m][k] (lda); Bt fp32 [n][k] (ldb). 256 thr, warp tile 32 x BN/2.
// flags: 1=bias, 2=residual, 4=relu, 8=causal(+scale)
// ---------------------------------------------------------------------------
template<int BN>
__global__ void __launch_bounds__(256, 2)
gemm_tc(const float* __restrict__ A, const float* __restrict__ Bt,
        const float* __restrict__ bias, const float* __restrict__ Res,
        float* __restrict__ C, int K, int lda, int ldb, int ldc, int zdiv,
        long sAb, long sAh, long sBb, long sBh, long sCb, long sCh,
        int flags, float scale)
{
    constexpr int ST = 20;                 // smem row stride (words)
    constexpr int ABUF = 128 * ST, BBUF = BN * ST;
    constexpr int WN = BN / 2, G = WN / 16;

    const int zb = blockIdx.z / zdiv, zh = blockIdx.z % zdiv;
    A  += zb * sAb + zh * sAh;
    Bt += zb * sBb + zh * sBh;
    const long coff = (long)zb * sCb + (long)zh * sCh;

    const int m0 = blockIdx.x * 128;
    const int n0 = blockIdx.y * BN;
    const int tid = threadIdx.x;

    const bool causal = (flags & 8) != 0;
    if (causal && n0 > m0 + 127) {
        const float4 mv = make_float4(-1e30f, -1e30f, -1e30f, -1e30f);
        const int col = (tid & 31) * 4, row = tid >> 5;
        #pragma unroll
        for (int r = 0; r < 16; r++)
            *(float4*)(C + coff + (long)(m0 + row + r * 8) * ldc + n0 + col) = mv;
        return;
    }

    __shared__ __align__(16) unsigned As[2][ABUF];
    __shared__ __align__(16) unsigned Bs[2][BBUF];

    // fill mappings
    const int arow = tid >> 2, acol = (tid & 3) * 4;
    const float* Ap = A + (long)(m0 + arow) * lda + acol;
    int bn, bk;
    if (BN == 128) { bn = tid >> 1; bk = (tid & 1) * 8; }
    else           { bn = tid >> 2; bk = (tid & 3) * 4; }
    const float* Bp = Bt + (long)(n0 + bn) * ldb + bk;

    const int lane = tid & 31, wid = tid >> 5;
    const int wm = wid & 3, wn = wid >> 2;
    const int grp = lane >> 2, qd = lane & 3;

    const unsigned aAddr = (unsigned)__cvta_generic_to_shared(
        &As[0][(wm * 32 + (lane & 15)) * ST + ((lane & 16) >> 2)]);
    const unsigned bAddr = (unsigned)__cvta_generic_to_shared(
        &Bs[0][(wn * WN + (lane & 15)) * ST + ((lane & 16) >> 2)]);

    float acc[2][2 * G][4];
    #pragma unroll
    for (int i = 0; i < 2; i++)
        #pragma unroll
        for (int j = 0; j < 2 * G; j++)
            #pragma unroll
            for (int l = 0; l < 4; l++) acc[i][j][l] = 0.f;

    const int nit = K / 16;
    float4 ra0, ra1, rb0, rb1;

    // prologue
    ra0 = *(const float4*)Ap;
    ra1 = *(const float4*)(Ap + 64 * lda);
    rb0 = *(const float4*)Bp;
    if (BN == 128) rb1 = *(const float4*)(Bp + 4);
    *(uint4*)&As[0][arow * ST + acol] =
        make_uint4(f2tf(ra0.x), f2tf(ra0.y), f2tf(ra0.z), f2tf(ra0.w));
    *(uint4*)&As[0][(arow + 64) * ST + acol] =
        make_uint4(f2tf(ra1.x), f2tf(ra1.y), f2tf(ra1.z), f2tf(ra1.w));
    *(uint4*)&Bs[0][bn * ST + bk] =
        make_uint4(f2tf(rb0.x), f2tf(rb0.y), f2tf(rb0.z), f2tf(rb0.w));
    if (BN == 128)
        *(uint4*)&Bs[0][bn * ST + bk + 4] =
            make_uint4(f2tf(rb1.x), f2tf(rb1.y), f2tf(rb1.z), f2tf(rb1.w));
    __syncthreads();

    for (int it = 0; it < nit; it++) {
        const int cur = it & 1;
        const bool more = (it + 1 < nit);
        if (more) {
            const float* Ap2 = Ap + (it + 1) * 16;
            const float* Bp2 = Bp + (it + 1) * 16;
            ra0 = *(const float4*)Ap2;
            ra1 = *(const float4*)(Ap2 + 64 * lda);
            rb0 = *(const float4*)Bp2;
            if (BN == 128) rb1 = *(const float4*)(Bp2 + 4);
        }

        const unsigned aC = aAddr + cur * (ABUF * 4);
        const unsigned bC = bAddr + cur * (BBUF * 4);
        #pragma unroll
        for (int ks = 0; ks < 2; ks++) {
            const uint4 a0 = ldm4(aC + (ks * 8) * 4);
            const uint4 a1 = ldm4(aC + (16 * ST + ks * 8) * 4);
            #pragma unroll
            for (int p = 0; p < G; p++) {
                const uint4 bv = ldm4(bC + (p * 16 * ST + ks * 8) * 4);
                mma8(acc[0][2 * p],     a0, bv.x, bv.z);
                mma8(acc[0][2 * p + 1], a0, bv.y, bv.w);
                mma8(acc[1][2 * p],     a1, bv.x, bv.z);
                mma8(acc[1][2 * p + 1], a1, bv.y, bv.w);
            }
        }

        if (more) {
            const int nx = cur ^ 1;
            *(uint4*)&As[nx][arow * ST + acol] =
                make_uint4(f2tf(ra0.x), f2tf(ra0.y), f2tf(ra0.z), f2tf(ra0.w));
            *(uint4*)&As[nx][(arow + 64) * ST + acol] =
                make_uint4(f2tf(ra1.x), f2tf(ra1.y), f2tf(ra1.z), f2tf(ra1.w));
            *(uint4*)&Bs[nx][bn * ST + bk] =
                make_uint4(f2tf(rb0.x), f2tf(rb0.y), f2tf(rb0.z), f2tf(rb0.w));
            if (BN == 128)
                *(uint4*)&Bs[nx][bn * ST + bk + 4] =
                    make_uint4(f2tf(rb1.x), f2tf(rb1.y), f2tf(rb1.z), f2tf(rb1.w));
        }
        __syncthreads();
    }

    const bool dob = flags & 1, dores = flags & 2, dorelu = flags & 4;
    #pragma unroll
    for (int mt = 0; mt < 2; mt++) {
        #pragma unroll
        for (int nt = 0; nt < 2 * G; nt++) {
            const int r = m0 + wm * 32 + mt * 16 + grp;
            const int c = n0 + wn * WN + nt * 8 + qd * 2;
            #pragma unroll
            for (int hf = 0; hf < 2; hf++) {
                const int rr = r + hf * 8;
                float v0 = acc[mt][nt][hf * 2 + 0];
                float v1 = acc[mt][nt][hf * 2 + 1];
                if (dob) { v0 += bias[c]; v1 += bias[c + 1]; }
                if (dores) {
                    const float* rp = Res + coff + (long)rr * ldc + c;
                    v0 += rp[0]; v1 += rp[1];
                }
                if (dorelu) { v0 = fmaxf(v0, 0.f); v1 = fmaxf(v1, 0.f); }
                if (causal) {
                    v0 = (c     <= rr) ? v0 * scale : -1e30f;
                    v1 = (c + 1 <= rr) ? v1 * scale : -1e30f;
                }
                *(float2*)(C + coff + (long)rr * ldc + c) = make_float2(v0, v1);
            }
        }
    }
}

// ---------------------------------------------------------------------------
__global__ void __launch_bounds__(256)
softmax_kernel(float* __restrict__ sc)
{
    float* p = sc + (long)blockIdx.x * NS;
    const int tid = threadIdx.x;
    __shared__ float red[256];
    float vals[4];
    float lm = -1e30f;
    #pragma unroll
    for (int i = 0; i < 4; i++) { vals[i] = p[tid + i * 256]; lm = fmaxf(lm, vals[i]); }
    red[tid] = lm; __syncthreads();
    for (int s = 128; s > 0; s >>= 1) {
        if (tid < s) red[tid] = fmaxf(red[tid], red[tid + s]);
        __syncthreads();
    }
    const float mx = red[0]; __syncthreads();
    float ls = 0.f;
    #pragma unroll
    for (int i = 0; i < 4; i++) { vals[i] = expf(vals[i] - mx); ls += vals[i]; }
    red[tid] = ls; __syncthreads();
    for (int s = 128; s > 0; s >>= 1) {
        if (tid < s) red[tid] += red[tid + s];
        __syncthreads();
    }
    const float inv = 1.f / red[0];
    #pragma unroll
    for (int i = 0; i < 4; i++) p[tid + i * 256] = vals[i] * inv;
}

__global__ void __launch_bounds__(256)
ln_kernel(const float* __restrict__ in, const float* __restrict__ g,
          const float* __restrict__ b, float* __restrict__ out)
{
    const float* p = in + (long)blockIdx.x * DM;
    float* po = out + (long)blockIdx.x * DM;
    const int tid = threadIdx.x;
    __shared__ float red[256];
    float vals[4];
    float s = 0.f;
    #pragma unroll
    for (int i = 0; i < 4; i++) { vals[i] = p[tid + i * 256]; s += vals[i]; }
    red[tid] = s; __syncthreads();
    for (int st = 128; st > 0; st >>= 1) {
        if (tid < st) red[tid] += red[tid + st];
        __syncthreads();
    }
    const float mean = red[0] * (1.f / DM); __syncthreads();
    float sq = 0.f;
    #pragma unroll
    for (int i = 0; i < 4; i++) { float d = vals[i] - mean; sq += d * d; }
    red[tid] = sq; __syncthreads();
    for (int st = 128; st > 0; st >>= 1) {
        if (tid < st) red[tid] += red[tid + st];
        __syncthreads();
    }
    const float sd = sqrtf(red[0] / (DM - 1));
    const float inv = 1.f / (sd + 1e-6f);
    #pragma unroll
    for (int i = 0; i < 4; i++) {
        const int d = tid + i * 256;
        po[d] = g[d] * (vals[i] - mean) * inv + b[d];
    }
}

__global__ void __launch_bounds__(256)
embed_kernel(const int* __restrict__ tokens, const float* __restrict__ emb,
             float* __restrict__ x)
{
    const int t = blockIdx.x;
    const int s = t & (NS - 1);
    const float* e = emb + (long)tokens[t] * DM;
    float* xo = x + (long)t * DM;
    const float nlog = -9.210340371976184f / (float)DM;
    for (int d = threadIdx.x; d < DM; d += 256) {
        const float freq = expf((float)(d & ~1) * nlog);
        const float ang = (float)s * freq;
        xo[d] = e[d] * 32.0f + ((d & 1) ? cosf(ang) : sinf(ang));
    }
}

// ---------------------------------------------------------------------------
extern "C" void kernel_launch(void* const* d_in, const int* in_sizes, int n_in,
                              void* d_out, int out_size)
{
    const int*   tokens = (const int*)  d_in[0];
    const float* emb    = (const float*)d_in[1];
    const float* Wq     = (const float*)d_in[2];
    const float* Wk     = (const float*)d_in[3];
    const float* Wv     = (const float*)d_in[4];
    const float* Wo     = (const float*)d_in[5];
    const float* bo     = (const float*)d_in[6];
    const float* ln1g   = (const float*)d_in[7];
    const float* ln1b   = (const float*)d_in[8];
    const float* W1     = (const float*)d_in[9];
    const float* b1     = (const float*)d_in[10];
    const float* W2     = (const float*)d_in[11];
    const float* b2     = (const float*)d_in[12];
    const float* ln2g   = (const float*)d_in[13];
    const float* ln2b   = (const float*)d_in[14];
    const float* Wout   = (const float*)d_in[15];
    const float* bout   = (const float*)d_in[16];
    float* out = (float*)d_out;

    float *x, *res, *qkv, *o, *ffn, *vt, *sc, *bt;
    cudaGetSymbolAddress((void**)&x,   g_x);
    cudaGetSymbolAddress((void**)&res, g_res);
    cudaGetSymbolAddress((void**)&qkv, g_qkv);
    cudaGetSymbolAddress((void**)&o,   g_o);
    cudaGetSymbolAddress((void**)&ffn, g_ffn);
    cudaGetSymbolAddress((void**)&vt,  g_vt);
    cudaGetSymbolAddress((void**)&sc,  g_sc);
    cudaGetSymbolAddress((void**)&bt,  g_bt);

    float* q = qkv;
    float* k = qkv + NT * DM;
    float* v = qkv + 2 * NT * DM;
    const long HW = (long)NH * DM * DH;   // 1M: per-layer QKV weight block

    embed_kernel<<<NT, 256>>>(tokens, emb, x);

    for (int l = 0; l < NL; l++) {
        // --- QKV: transpose weights per head -> bt[(h*64+n)*DM + k]
        tr32<<<dim3(DM / 32, DH / 32, NH), 256>>>(Wq + l * HW, bt,          DM, DH, DH, NH, 0, (long)DM * DH);
        tr32<<<dim3(DM / 32, DH / 32, NH), 256>>>(Wk + l * HW, bt + HW,     DM, DH, DH, NH, 0, (long)DM * DH);
        tr32<<<dim3(DM / 32, DH / 32, NH), 256>>>(Wv + l * HW, bt + 2 * HW, DM, DH, DH, NH, 0, (long)DM * DH);
        gemm_tc<128><<<dim3(NT / 128, DM / 128, 3), 256>>>(
            x, bt, nullptr, nullptr, qkv, DM, DM, DM, DM, 3,
            0, 0, 0, HW, 0, (long)NT * DM, 0, 1.f);

        // --- V transpose per head: vt[(z*64+c)*NS + j]
        tr32<<<dim3(NS / 32, DH / 32, NB * NH), 256>>>(
            v, vt, NS, DH, DM, NH, (long)NS * DM, DH);

        // --- scores = Q K^T / 8, causal (K already [j][c] = [n][k])
        gemm_tc<128><<<dim3(NS / 128, NS / 128, NB * NH), 256>>>(
            q, k, nullptr, nullptr, sc, DH, DM, DM, NS, NH,
            (long)NS * DM, DH, (long)NS * DM, DH,
            (long)NH * NS * NS, (long)NS * NS, 8, 0.125f);

        softmax_kernel<<<NB * NH * NS, 256>>>(sc);

        // --- O = P V  (B = vt [c][j])
        gemm_tc<64><<<dim3(NS / 128, 1, NB * NH), 256>>>(
            sc, vt, nullptr, nullptr, o, NS, NS, NS, DM, NH,
            (long)NH * NS * NS, (long)NS * NS, (long)NH * DH * NS, (long)DH * NS,
            (long)NS * DM, DH, 0, 1.f);

        // --- O projection + bias + residual
        tr32<<<dim3(DM / 32, DM / 32, 1), 256>>>(Wo + (long)l * DM * DM, bt, DM, DM, DM, 1, 0, 0);
        gemm_tc<128><<<dim3(NT / 128, DM / 128), 256>>>(
            o, bt, bo + l * DM, x, res, DM, DM, DM, DM, 1,
            0, 0, 0, 0, 0, 0, 1 | 2, 1.f);
        ln_kernel<<<NT, 256>>>(res, ln1g + l * DM, ln1b + l * DM, x);

        // --- FFN
        tr32<<<dim3(DM / 32, DFF / 32, 1), 256>>>(W1 + (long)l * DM * DFF, bt, DM, DFF, DFF, 1, 0, 0);
        gemm_tc<128><<<dim3(NT / 128, DFF / 128), 256>>>(
            x, bt, b1 + l * DFF, nullptr, ffn, DM, DM, DM, DFF, 1,
            0, 0, 0, 0, 0, 0, 1 | 4, 1.f);
        tr32<<<dim3(DFF / 32, DM / 32, 1), 256>>>(W2 + (long)l * DFF * DM, bt, DFF, DM, DM, 1, 0, 0);
        gemm_tc<128><<<dim3(NT / 128, DM / 128), 256>>>(
            ffn, bt, b2 + l * DM, x, res, DFF, DFF, DFF, DM, 1,
            0, 0, 0, 0, 0, 0, 1 | 2, 1.f);
        ln_kernel<<<NT, 256>>>(res, ln2g + l * DM, ln2b + l * DM, x);
    }

    // --- final vocab projection
    tr32<<<dim3(DM / 32, NV / 32, 1), 256>>>(Wout, bt, DM, NV, NV, 1, 0, 0);
    gemm_tc<128><<<dim3(NT / 128, NV / 128), 256>>>(
        x, bt, bout, nullptr, out, DM, DM, DM, NV, 1,
        0, 0, 0, 0, 0, 0, 1, 1.f);
}

// round 5
// speedup vs baseline: 1.1115x; 1.1115x over previous
#include <cuda_runtime.h>
#include <cstdint>

constexpr int NL  = 6;
constexpr int NH  = 16;
constexpr int DM  = 1024;
constexpr int DH  = 64;
constexpr int DFF = 4096;
constexpr int NV  = 32000;
constexpr int NB  = 2;
constexpr int NS  = 1024;
constexpr int NT  = NB * NS;

__device__ float g_x  [NT * DM];                 // fp32 (residual path)
__device__ float g_xr [NT * DM];                 // tf32-rounded copy
__device__ float g_res[NT * DM];
__device__ float g_qkv[3 * NT * DM];             // rounded
__device__ float g_o  [NT * DM];                 // rounded
__device__ float g_ffn[NT * DFF];                // rounded
__device__ float g_vt [NB * NH * DH * NS];       // rounded
__device__ float g_sc [(long)NB * NH * NS * NS]; // rounded (post-softmax)
__device__ float g_bt [(long)NV * DM];           // rounded transposed weights

__device__ __forceinline__ float f2tff(float f) {
    unsigned u;
    asm("cvt.rna.tf32.f32 %0, %1;" : "=r"(u) : "f"(f));
    return __uint_as_float(u);
}
__device__ __forceinline__ void mma8(float* c, const uint4& a, unsigned b0, unsigned b1) {
    asm volatile(
        "mma.sync.aligned.m16n8k8.row.col.f32.tf32.tf32.f32 "
        "{%0,%1,%2,%3}, {%4,%5,%6,%7}, {%8,%9}, {%0,%1,%2,%3};"
        : "+f"(c[0]), "+f"(c[1]), "+f"(c[2]), "+f"(c[3])
        : "r"(a.x), "r"(a.y), "r"(a.z), "r"(a.w), "r"(b0), "r"(b1));
}
__device__ __forceinline__ uint4 ldm4(unsigned addr) {
    uint4 r;
    asm volatile("ldmatrix.sync.aligned.m8n8.x4.shared.b16 {%0,%1,%2,%3}, [%4];"
                 : "=r"(r.x), "=r"(r.y), "=r"(r.z), "=r"(r.w) : "r"(addr));
    return r;
}
__device__ __forceinline__ void cp16(unsigned sm, const void* g) {
    asm volatile("cp.async.ca.shared.global [%0], [%1], 16;" :: "r"(sm), "l"(g));
}
#define CP_COMMIT asm volatile("cp.async.commit_group;" ::: "memory")
#define CP_WAIT2  asm volatile("cp.async.wait_group 2;" ::: "memory")

// ---------------------------------------------------------------------------
// Transpose + tf32 round: in (per z: [K][N], ld ldin) -> out[(z*N+n)*K + k]
// ---------------------------------------------------------------------------
__global__ void __launch_bounds__(256)
tr32(const float* __restrict__ in, float* __restrict__ out,
     int K, int N, int ldin, int zdiv, long sZb, long sZh)
{
    __shared__ float t[32][33];
    const int z = blockIdx.z, zb = z / zdiv, zh = z % zdiv;
    in += zb * sZb + zh * sZh;
    const int k0 = blockIdx.x * 32, n0 = blockIdx.y * 32;
    const int tx = threadIdx.x & 31, ty = threadIdx.x >> 5;
    #pragma unroll
    for (int r = 0; r < 32; r += 8)
        t[ty + r][tx] = in[(long)(k0 + ty + r) * ldin + n0 + tx];
    __syncthreads();
    #pragma unroll
    for (int r = 0; r < 32; r += 8)
        out[((long)z * N + n0 + ty + r) * K + k0 + tx] = f2tff(t[tx][ty + r]);
}

// ---------------------------------------------------------------------------
// tf32 TC GEMM, 4-stage cp.async pipeline, ldmatrix both operands.
// A [m][k] (pre-rounded), Bt [n][k] (pre-rounded). BM=128, BK=16, BN 128/64.
// flags: 1=bias, 2=residual, 4=relu, 8=causal(+scale), 16=round output
// ---------------------------------------------------------------------------
template<int BN>
__global__ void __launch_bounds__(256, 2)
gemm_tc(const float* __restrict__ A, const float* __restrict__ Bt,
        const float* __restrict__ bias, const float* __restrict__ Res,
        float* __restrict__ C, int K, int lda, int ldb, int ldc, int zdiv,
        long sAb, long sAh, long sBb, long sBh, long sCb, long sCh,
        int flags, float scale)
{
    constexpr int ST = 20;                     // words per 16-float row
    constexpr int ABUF = 128 * ST, BBUF = BN * ST;
    constexpr int WN = BN / 2, G = WN / 16;

    extern __shared__ unsigned smem[];
    unsigned* Asm = smem;
    unsigned* Bsm = smem + 4 * ABUF;

    const int zb = blockIdx.z / zdiv, zh = blockIdx.z % zdiv;
    A  += zb * sAb + zh * sAh;
    Bt += zb * sBb + zh * sBh;
    const long coff = (long)zb * sCb + (long)zh * sCh;

    const int m0 = blockIdx.x * 128;
    const int n0 = blockIdx.y * BN;
    const int tid = threadIdx.x;

    const bool causal = (flags & 8) != 0;
    if (causal && n0 > m0 + 127) {
        const float4 mv = make_float4(-1e30f, -1e30f, -1e30f, -1e30f);
        const int col = (tid & 31) * 4, row = tid >> 5;
        #pragma unroll
        for (int r = 0; r < 16; r++)
            *(float4*)(C + coff + (long)(m0 + row + r * 8) * ldc + n0 + col) = mv;
        return;
    }

    // fill mappings (16B cp.async chunks)
    const int ar = tid >> 1, aw = (tid & 1) * 8;
    const float* Ag = A + (long)(m0 + ar) * lda + aw;
    const unsigned aDst = (unsigned)__cvta_generic_to_shared(&Asm[ar * ST + aw]);
    int bn, bw;
    if (BN == 128) { bn = tid >> 1; bw = (tid & 1) * 8; }
    else           { bn = tid >> 2; bw = (tid & 3) * 4; }
    const float* Bg = Bt + (long)(n0 + bn) * ldb + bw;
    const unsigned bDst = (unsigned)__cvta_generic_to_shared(&Bsm[bn * ST + bw]);

    const int nit = K / 16;
    auto fill = [&](int s) {
        const int st = s & 3;
        const unsigned ao = aDst + st * (ABUF * 4);
        const float* ag = Ag + s * 16;
        cp16(ao, ag); cp16(ao + 16, ag + 4);
        const unsigned bo = bDst + st * (BBUF * 4);
        const float* bg = Bg + s * 16;
        cp16(bo, bg);
        if (BN == 128) cp16(bo + 16, bg + 4);
    };

    const int lane = tid & 31, wid = tid >> 5;
    const int wm = wid & 3, wn = wid >> 2;
    const int grp = lane >> 2, qd = lane & 3;

    const unsigned aAddr = (unsigned)__cvta_generic_to_shared(
        &Asm[(wm * 32 + (lane & 15)) * ST + ((lane & 16) >> 2)]);
    const unsigned bAddr = (unsigned)__cvta_generic_to_shared(
        &Bsm[(wn * WN + (lane & 15)) * ST + ((lane & 16) >> 2)]);

    float acc[2][2 * G][4];
    #pragma unroll
    for (int i = 0; i < 2; i++)
        #pragma unroll
        for (int j = 0; j < 2 * G; j++)
            #pragma unroll
            for (int l = 0; l < 4; l++) acc[i][j][l] = 0.f;

    #pragma unroll
    for (int s = 0; s < 3; s++) { if (s < nit) fill(s); CP_COMMIT; }

    for (int it = 0; it < nit; it++) {
        CP_WAIT2;
        __syncthreads();
        if (it + 3 < nit) fill(it + 3);
        CP_COMMIT;

        const unsigned aC = aAddr + (it & 3) * (ABUF * 4);
        const unsigned bC = bAddr + (it & 3) * (BBUF * 4);
        #pragma unroll
        for (int ks = 0; ks < 2; ks++) {
            const uint4 a0 = ldm4(aC + (ks * 8) * 4);
            const uint4 a1 = ldm4(aC + (16 * ST + ks * 8) * 4);
            #pragma unroll
            for (int p = 0; p < G; p++) {
                const uint4 bv = ldm4(bC + (p * 16 * ST + ks * 8) * 4);
                mma8(acc[0][2 * p],     a0, bv.x, bv.z);
                mma8(acc[0][2 * p + 1], a0, bv.y, bv.w);
                mma8(acc[1][2 * p],     a1, bv.x, bv.z);
                mma8(acc[1][2 * p + 1], a1, bv.y, bv.w);
            }
        }
    }

    const bool dob = flags & 1, dores = flags & 2, dorelu = flags & 4,
               dornd = flags & 16;
    #pragma unroll
    for (int mt = 0; mt < 2; mt++) {
        #pragma unroll
        for (int nt = 0; nt < 2 * G; nt++) {
            const int r = m0 + wm * 32 + mt * 16 + grp;
            const int c = n0 + wn * WN + nt * 8 + qd * 2;
            #pragma unroll
            for (int hf = 0; hf < 2; hf++) {
                const int rr = r + hf * 8;
                float v0 = acc[mt][nt][hf * 2 + 0];
                float v1 = acc[mt][nt][hf * 2 + 1];
                if (dob) { v0 += bias[c]; v1 += bias[c + 1]; }
                if (dores) {
                    const float* rp = Res + coff + (long)rr * ldc + c;
                    v0 += rp[0]; v1 += rp[1];
                }
                if (dorelu) { v0 = fmaxf(v0, 0.f); v1 = fmaxf(v1, 0.f); }
                if (causal) {
                    v0 = (c     <= rr) ? v0 * scale : -1e30f;
                    v1 = (c + 1 <= rr) ? v1 * scale : -1e30f;
                }
                if (dornd) { v0 = f2tff(v0); v1 = f2tff(v1); }
                *(float2*)(C + coff + (long)rr * ldc + c) = make_float2(v0, v1);
            }
        }
    }
}

// ---------------------------------------------------------------------------
__global__ void __launch_bounds__(256)
softmax_kernel(float* __restrict__ sc)
{
    float* p = sc + (long)blockIdx.x * NS;
    const int tid = threadIdx.x;
    __shared__ float red[256];
    float vals[4];
    float lm = -1e30f;
    #pragma unroll
    for (int i = 0; i < 4; i++) { vals[i] = p[tid + i * 256]; lm = fmaxf(lm, vals[i]); }
    red[tid] = lm; __syncthreads();
    for (int s = 128; s > 0; s >>= 1) {
        if (tid < s) red[tid] = fmaxf(red[tid], red[tid + s]);
        __syncthreads();
    }
    const float mx = red[0]; __syncthreads();
    float ls = 0.f;
    #pragma unroll
    for (int i = 0; i < 4; i++) { vals[i] = expf(vals[i] - mx); ls += vals[i]; }
    red[tid] = ls; __syncthreads();
    for (int s = 128; s > 0; s >>= 1) {
        if (tid < s) red[tid] += red[tid + s];
        __syncthreads();
    }
    const float inv = 1.f / red[0];
    #pragma unroll
    for (int i = 0; i < 4; i++) p[tid + i * 256] = f2tff(vals[i] * inv);
}

__global__ void __launch_bounds__(256)
ln_kernel(const float* __restrict__ in, const float* __restrict__ g,
          const float* __restrict__ b, float* __restrict__ out,
          float* __restrict__ outr)
{
    const float* p = in + (long)blockIdx.x * DM;
    float* po  = out  + (long)blockIdx.x * DM;
    float* por = outr + (long)blockIdx.x * DM;
    const int tid = threadIdx.x;
    __shared__ float red[256];
    float vals[4];
    float s = 0.f;
    #pragma unroll
    for (int i = 0; i < 4; i++) { vals[i] = p[tid + i * 256]; s += vals[i]; }
    red[tid] = s; __syncthreads();
    for (int st = 128; st > 0; st >>= 1) {
        if (tid < st) red[tid] += red[tid + st];
        __syncthreads();
    }
    const float mean = red[0] * (1.f / DM); __syncthreads();
    float sq = 0.f;
    #pragma unroll
    for (int i = 0; i < 4; i++) { float d = vals[i] - mean; sq += d * d; }
    red[tid] = sq; __syncthreads();
    for (int st = 128; st > 0; st >>= 1) {
        if (tid < st) red[tid] += red[tid + st];
        __syncthreads();
    }
    const float sd = sqrtf(red[0] / (DM - 1));
    const float inv = 1.f / (sd + 1e-6f);
    #pragma unroll
    for (int i = 0; i < 4; i++) {
        const int d = tid + i * 256;
        const float r = g[d] * (vals[i] - mean) * inv + b[d];
        po[d] = r;
        por[d] = f2tff(r);
    }
}

__global__ void __launch_bounds__(256)
embed_kernel(const int* __restrict__ tokens, const float* __restrict__ emb,
             float* __restrict__ x, float* __restrict__ xr)
{
    const int t = blockIdx.x;
    const int s = t & (NS - 1);
    const float* e = emb + (long)tokens[t] * DM;
    float* xo  = x  + (long)t * DM;
    float* xro = xr + (long)t * DM;
    const float nlog = -9.210340371976184f / (float)DM;
    for (int d = threadIdx.x; d < DM; d += 256) {
        const float freq = expf((float)(d & ~1) * nlog);
        const float ang = (float)s * freq;
        const float r = e[d] * 32.0f + ((d & 1) ? cosf(ang) : sinf(ang));
        xo[d] = r;
        xro[d] = f2tff(r);
    }
}

// ---------------------------------------------------------------------------
extern "C" void kernel_launch(void* const* d_in, const int* in_sizes, int n_in,
                              void* d_out, int out_size)
{
    const int*   tokens = (const int*)  d_in[0];
    const float* emb    = (const float*)d_in[1];
    const float* Wq     = (const float*)d_in[2];
    const float* Wk     = (const float*)d_in[3];
    const float* Wv     = (const float*)d_in[4];
    const float* Wo     = (const float*)d_in[5];
    const float* bo     = (const float*)d_in[6];
    const float* ln1g   = (const float*)d_in[7];
    const float* ln1b   = (const float*)d_in[8];
    const float* W1     = (const float*)d_in[9];
    const float* b1     = (const float*)d_in[10];
    const float* W2     = (const float*)d_in[11];
    const float* b2     = (const float*)d_in[12];
    const float* ln2g   = (const float*)d_in[13];
    const float* ln2b   = (const float*)d_in[14];
    const float* Wout   = (const float*)d_in[15];
    const float* bout   = (const float*)d_in[16];
    float* out = (float*)d_out;

    float *x, *xr, *res, *qkv, *o, *ffn, *vt, *sc, *bt;
    cudaGetSymbolAddress((void**)&x,   g_x);
    cudaGetSymbolAddress((void**)&xr,  g_xr);
    cudaGetSymbolAddress((void**)&res, g_res);
    cudaGetSymbolAddress((void**)&qkv, g_qkv);
    cudaGetSymbolAddress((void**)&o,   g_o);
    cudaGetSymbolAddress((void**)&ffn, g_ffn);
    cudaGetSymbolAddress((void**)&vt,  g_vt);
    cudaGetSymbolAddress((void**)&sc,  g_sc);
    cudaGetSymbolAddress((void**)&bt,  g_bt);

    constexpr int SM128 = 4 * (128 * 20 + 128 * 20) * 4;  // 81920
    constexpr int SM64  = 4 * (128 * 20 + 64 * 20) * 4;   // 61440
    cudaFuncSetAttribute(gemm_tc<128>, cudaFuncAttributeMaxDynamicSharedMemorySize, SM128);
    cudaFuncSetAttribute(gemm_tc<64>,  cudaFuncAttributeMaxDynamicSharedMemorySize, SM64);

    float* q = qkv;
    float* k = qkv + NT * DM;
    float* v = qkv + 2 * NT * DM;
    const long HW = (long)NH * DM * DH;

    embed_kernel<<<NT, 256>>>(tokens, emb, x, xr);

    for (int l = 0; l < NL; l++) {
        // QKV weights: per-head transpose -> bt[(h*64+n)*DM + k] (rounded)
        tr32<<<dim3(DM / 32, DH / 32, NH), 256>>>(Wq + l * HW, bt,          DM, DH, DH, NH, 0, (long)DM * DH);
        tr32<<<dim3(DM / 32, DH / 32, NH), 256>>>(Wk + l * HW, bt + HW,     DM, DH, DH, NH, 0, (long)DM * DH);
        tr32<<<dim3(DM / 32, DH / 32, NH), 256>>>(Wv + l * HW, bt + 2 * HW, DM, DH, DH, NH, 0, (long)DM * DH);
        gemm_tc<128><<<dim3(NT / 128, DM / 128, 3), 256, SM128>>>(
            xr, bt, nullptr, nullptr, qkv, DM, DM, DM, DM, 3,
            0, 0, 0, HW, 0, (long)NT * DM, 16, 1.f);

        // V transpose per head (rounded; idempotent)
        tr32<<<dim3(NS / 32, DH / 32, NB * NH), 256>>>(
            v, vt, NS, DH, DM, NH, (long)NS * DM, DH);

        // scores = Q K^T / 8, causal
        gemm_tc<128><<<dim3(NS / 128, NS / 128, NB * NH), 256, SM128>>>(
            q, k, nullptr, nullptr, sc, DH, DM, DM, NS, NH,
            (long)NS * DM, DH, (long)NS * DM, DH,
            (long)NH * NS * NS, (long)NS * NS, 8, 0.125f);

        softmax_kernel<<<NB * NH * NS, 256>>>(sc);

        // O = P V (rounded output)
        gemm_tc<64><<<dim3(NS / 128, 1, NB * NH), 256, SM64>>>(
            sc, vt, nullptr, nullptr, o, NS, NS, NS, DM, NH,
            (long)NH * NS * NS, (long)NS * NS, (long)NH * DH * NS, (long)DH * NS,
            (long)NS * DM, DH, 16, 1.f);

        // O projection + bias + residual (fp32 out)
        tr32<<<dim3(DM / 32, DM / 32, 1), 256>>>(Wo + (long)l * DM * DM, bt, DM, DM, DM, 1, 0, 0);
        gemm_tc<128><<<dim3(NT / 128, DM / 128), 256, SM128>>>(
            o, bt, bo + l * DM, x, res, DM, DM, DM, DM, 1,
            0, 0, 0, 0, 0, 0, 1 | 2, 1.f);
        ln_kernel<<<NT, 256>>>(res, ln1g + l * DM, ln1b + l * DM, x, xr);

        // FFN
        tr32<<<dim3(DM / 32, DFF / 32, 1), 256>>>(W1 + (long)l * DM * DFF, bt, DM, DFF, DFF, 1, 0, 0);
        gemm_tc<128><<<dim3(NT / 128, DFF / 128), 256, SM128>>>(
            xr, bt, b1 + l * DFF, nullptr, ffn, DM, DM, DM, DFF, 1,
            0, 0, 0, 0, 0, 0, 1 | 4 | 16, 1.f);
        tr32<<<dim3(DFF / 32, DM / 32, 1), 256>>>(W2 + (long)l * DFF * DM, bt, DFF, DM, DM, 1, 0, 0);
        gemm_tc<128><<<dim3(NT / 128, DM / 128), 256, SM128>>>(
            ffn, bt, b2 + l * DM, x, res, DFF, DFF, DFF, DM, 1,
            0, 0, 0, 0, 0, 0, 1 | 2, 1.f);
        ln_kernel<<<NT, 256>>>(res, ln2g + l * DM, ln2b + l * DM, x, xr);
    }

    // final vocab projection
    tr32<<<dim3(DM / 32, NV / 32, 1), 256>>>(Wout, bt, DM, NV, NV, 1, 0, 0);
    gemm_tc<128><<<dim3(NT / 128, NV / 128), 256, SM128>>>(
        xr, bt, bout, nullptr, out, DM, DM, DM, NV, 1,
        0, 0, 0, 0, 0, 0, 1, 1.f);
}

// round 6
// speedup vs baseline: 1.2234x; 1.1007x over previous
#include <cuda_runtime.h>
#include <cstdint>

constexpr int NL  = 6;
constexpr int NH  = 16;
constexpr int DM  = 1024;
constexpr int DH  = 64;
constexpr int DFF = 4096;
constexpr int NV  = 32000;
constexpr int NB  = 2;
constexpr int NS  = 1024;
constexpr int NT  = NB * NS;

__device__ float g_x  [NT * DM];                 // fp32 (residual path)
__device__ float g_xr [NT * DM];                 // tf32-rounded copy
__device__ float g_res[NT * DM];
__device__ float g_qkv[3 * NT * DM];             // rounded
__device__ float g_o  [NT * DM];                 // rounded
__device__ float g_ffn[NT * DFF];                // rounded
__device__ float g_vt [NB * NH * DH * NS];       // rounded V^T per head
__device__ float g_bt [(long)NV * DM];           // rounded transposed weights

__device__ __forceinline__ float f2tff(float f) {
    unsigned u;
    asm("cvt.rna.tf32.f32 %0, %1;" : "=r"(u) : "f"(f));
    return __uint_as_float(u);
}
__device__ __forceinline__ void mma8(float* c, const uint4& a, unsigned b0, unsigned b1) {
    asm volatile(
        "mma.sync.aligned.m16n8k8.row.col.f32.tf32.tf32.f32 "
        "{%0,%1,%2,%3}, {%4,%5,%6,%7}, {%8,%9}, {%0,%1,%2,%3};"
        : "+f"(c[0]), "+f"(c[1]), "+f"(c[2]), "+f"(c[3])
        : "r"(a.x), "r"(a.y), "r"(a.z), "r"(a.w), "r"(b0), "r"(b1));
}
__device__ __forceinline__ uint4 ldm4(unsigned addr) {
    uint4 r;
    asm volatile("ldmatrix.sync.aligned.m8n8.x4.shared.b16 {%0,%1,%2,%3}, [%4];"
                 : "=r"(r.x), "=r"(r.y), "=r"(r.z), "=r"(r.w) : "r"(addr));
    return r;
}
__device__ __forceinline__ void cp16(unsigned sm, const void* g) {
    asm volatile("cp.async.ca.shared.global [%0], [%1], 16;" :: "r"(sm), "l"(g));
}
#define CP_COMMIT asm volatile("cp.async.commit_group;" ::: "memory")
#define CP_WAIT2  asm volatile("cp.async.wait_group 2;" ::: "memory")
#define CP_WAIT0  asm volatile("cp.async.wait_group 0;" ::: "memory")

// ---------------------------------------------------------------------------
// Transpose + tf32 round: in (per z: [K][N], ld ldin) -> out[(z*N+n)*K + k]
// ---------------------------------------------------------------------------
__global__ void __launch_bounds__(256)
tr32(const float* __restrict__ in, float* __restrict__ out,
     int K, int N, int ldin, int zdiv, long sZb, long sZh)
{
    __shared__ float t[32][33];
    const int z = blockIdx.z, zb = z / zdiv, zh = z % zdiv;
    in += zb * sZb + zh * sZh;
    const int k0 = blockIdx.x * 32, n0 = blockIdx.y * 32;
    const int tx = threadIdx.x & 31, ty = threadIdx.x >> 5;
    #pragma unroll
    for (int r = 0; r < 32; r += 8)
        t[ty + r][tx] = in[(long)(k0 + ty + r) * ldin + n0 + tx];
    __syncthreads();
    #pragma unroll
    for (int r = 0; r < 32; r += 8)
        out[((long)z * N + n0 + ty + r) * K + k0 + tx] = f2tff(t[tx][ty + r]);
}

// ---------------------------------------------------------------------------
// tf32 TC GEMM, 4-stage cp.async pipeline, ldmatrix both operands.
// flags: 1=bias, 2=residual, 4=relu, 16=round output
// ---------------------------------------------------------------------------
template<int BN>
__global__ void __launch_bounds__(256, 2)
gemm_tc(const float* __restrict__ A, const float* __restrict__ Bt,
        const float* __restrict__ bias, const float* __restrict__ Res,
        float* __restrict__ C, int K, int lda, int ldb, int ldc, int zdiv,
        long sAb, long sAh, long sBb, long sBh, long sCb, long sCh,
        int flags)
{
    constexpr int ST = 20;
    constexpr int ABUF = 128 * ST, BBUF = BN * ST;
    constexpr int WN = BN / 2, G = WN / 16;

    extern __shared__ unsigned smem[];
    unsigned* Asm = smem;
    unsigned* Bsm = smem + 4 * ABUF;

    const int zb = blockIdx.z / zdiv, zh = blockIdx.z % zdiv;
    A  += zb * sAb + zh * sAh;
    Bt += zb * sBb + zh * sBh;
    const long coff = (long)zb * sCb + (long)zh * sCh;

    const int m0 = blockIdx.x * 128;
    const int n0 = blockIdx.y * BN;
    const int tid = threadIdx.x;

    const int ar = tid >> 1, aw = (tid & 1) * 8;
    const float* Ag = A + (long)(m0 + ar) * lda + aw;
    const unsigned aDst = (unsigned)__cvta_generic_to_shared(&Asm[ar * ST + aw]);
    int bn, bw;
    if (BN == 128) { bn = tid >> 1; bw = (tid & 1) * 8; }
    else           { bn = tid >> 2; bw = (tid & 3) * 4; }
    const float* Bg = Bt + (long)(n0 + bn) * ldb + bw;
    const unsigned bDst = (unsigned)__cvta_generic_to_shared(&Bsm[bn * ST + bw]);

    const int nit = K / 16;
    auto fill = [&](int s) {
        const int st = s & 3;
        const unsigned ao = aDst + st * (ABUF * 4);
        const float* ag = Ag + s * 16;
        cp16(ao, ag); cp16(ao + 16, ag + 4);
        const unsigned bo = bDst + st * (BBUF * 4);
        const float* bg = Bg + s * 16;
        cp16(bo, bg);
        if (BN == 128) cp16(bo + 16, bg + 4);
    };

    const int lane = tid & 31, wid = tid >> 5;
    const int wm = wid & 3, wn = wid >> 2;
    const int grp = lane >> 2, qd = lane & 3;

    const unsigned aAddr = (unsigned)__cvta_generic_to_shared(
        &Asm[(wm * 32 + (lane & 15)) * ST + ((lane & 16) >> 2)]);
    const unsigned bAddr = (unsigned)__cvta_generic_to_shared(
        &Bsm[(wn * WN + (lane & 15)) * ST + ((lane & 16) >> 2)]);

    float acc[2][2 * G][4];
    #pragma unroll
    for (int i = 0; i < 2; i++)
        #pragma unroll
        for (int j = 0; j < 2 * G; j++)
            #pragma unroll
            for (int l = 0; l < 4; l++) acc[i][j][l] = 0.f;

    #pragma unroll
    for (int s = 0; s < 3; s++) { if (s < nit) fill(s); CP_COMMIT; }

    for (int it = 0; it < nit; it++) {
        CP_WAIT2;
        __syncthreads();
        if (it + 3 < nit) fill(it + 3);
        CP_COMMIT;

        const unsigned aC = aAddr + (it & 3) * (ABUF * 4);
        const unsigned bC = bAddr + (it & 3) * (BBUF * 4);
        #pragma unroll
        for (int ks = 0; ks < 2; ks++) {
            const uint4 a0 = ldm4(aC + (ks * 8) * 4);
            const uint4 a1 = ldm4(aC + (16 * ST + ks * 8) * 4);
            #pragma unroll
            for (int p = 0; p < G; p++) {
                const uint4 bv = ldm4(bC + (p * 16 * ST + ks * 8) * 4);
                mma8(acc[0][2 * p],     a0, bv.x, bv.z);
                mma8(acc[0][2 * p + 1], a0, bv.y, bv.w);
                mma8(acc[1][2 * p],     a1, bv.x, bv.z);
                mma8(acc[1][2 * p + 1], a1, bv.y, bv.w);
            }
        }
    }

    const bool dob = flags & 1, dores = flags & 2, dorelu = flags & 4,
               dornd = flags & 16;
    #pragma unroll
    for (int mt = 0; mt < 2; mt++) {
        #pragma unroll
        for (int nt = 0; nt < 2 * G; nt++) {
            const int r = m0 + wm * 32 + mt * 16 + grp;
            const int c = n0 + wn * WN + nt * 8 + qd * 2;
            #pragma unroll
            for (int hf = 0; hf < 2; hf++) {
                const int rr = r + hf * 8;
                float v0 = acc[mt][nt][hf * 2 + 0];
                float v1 = acc[mt][nt][hf * 2 + 1];
                if (dob) { v0 += bias[c]; v1 += bias[c + 1]; }
                if (dores) {
                    const float* rp = Res + coff + (long)rr * ldc + c;
                    v0 += rp[0]; v1 += rp[1];
                }
                if (dorelu) { v0 = fmaxf(v0, 0.f); v1 = fmaxf(v1, 0.f); }
                if (dornd) { v0 = f2tff(v0); v1 = f2tff(v1); }
                *(float2*)(C + coff + (long)rr * ldc + c) = make_float2(v0, v1);
            }
        }
    }
}

// ---------------------------------------------------------------------------
// Flash attention: 128 q-rows per CTA, 64-wide j tiles, online softmax.
// q,k: rounded fp32 [tok][DM] head-interleaved; vt: rounded [z*64+c][NS].
// ---------------------------------------------------------------------------
constexpr int FST = 68;   // smem row stride (floats); 68*4=272B, 16B aligned
constexpr int FA_SMEM = (128 * FST + 64 * FST + 64 * FST + 128 * FST) * 4;

__global__ void __launch_bounds__(256, 2)
flash_attn(const float* __restrict__ q, const float* __restrict__ k,
           const float* __restrict__ vt, float* __restrict__ o)
{
    extern __shared__ float fsm[];
    float* Qs  = fsm;                   // [128][FST]
    float* Ks  = Qs  + 128 * FST;       // [64][FST]  rows j, cols c
    float* Vts = Ks  + 64 * FST;        // [64][FST]  rows c, cols j
    float* Ps  = Vts + 64 * FST;        // [128][FST] rows q, cols j

    const int z = blockIdx.y;
    const int b = z >> 4, h = z & 15;
    const int i0 = blockIdx.x * 128;
    const int tid = threadIdx.x, lane = tid & 31, w = tid >> 5;
    const int grp = lane >> 2, qd = lane & 3;

    {   // Q fill
        const int r = tid >> 1, cb = (tid & 1) * 32;
        const float* src = q + (long)(b * NS + i0 + r) * DM + h * DH + cb;
        unsigned dst = (unsigned)__cvta_generic_to_shared(Qs + r * FST + cb);
        #pragma unroll
        for (int i = 0; i < 8; i++) cp16(dst + i * 16, src + i * 4);
        CP_COMMIT;
    }

    const int r0 = w * 16;
    const int gr = i0 + r0 + grp;
    const unsigned qAddr = (unsigned)__cvta_generic_to_shared(
        Qs + (r0 + (lane & 15)) * FST + ((lane & 16) >> 2));
    const unsigned kAddr = (unsigned)__cvta_generic_to_shared(
        Ks + (lane & 15) * FST + ((lane & 16) >> 2));
    const unsigned vAddr = (unsigned)__cvta_generic_to_shared(
        Vts + (lane & 15) * FST + ((lane & 16) >> 2));
    const unsigned pAddr = (unsigned)__cvta_generic_to_shared(
        Ps + (r0 + (lane & 15)) * FST + ((lane & 16) >> 2));

    float m0 = -1e30f, m1 = -1e30f, l0 = 0.f, l1 = 0.f;
    float oacc[8][4];
    #pragma unroll
    for (int i = 0; i < 8; i++)
        #pragma unroll
        for (int j = 0; j < 4; j++) oacc[i][j] = 0.f;

    const int ntiles = i0 / 64 + 2;

    for (int jt = 0; jt < ntiles; jt++) {
        const int j0 = jt * 64;
        __syncthreads();            // prior tile fully consumed
        {   // K/V tile fill
            const int jj = tid >> 2, cb = (tid & 3) * 4;
            const float* ks = k + (long)(b * NS + j0 + jj) * DM + h * DH + cb;
            unsigned kd = (unsigned)__cvta_generic_to_shared(Ks + jj * FST + cb);
            #pragma unroll
            for (int i = 0; i < 4; i++) cp16(kd + i * 64, ks + i * 16);
            const float* vs = vt + ((long)z * DH + jj) * NS + j0 + cb;
            unsigned vd = (unsigned)__cvta_generic_to_shared(Vts + jj * FST + cb);
            #pragma unroll
            for (int i = 0; i < 4; i++) cp16(vd + i * 64, vs + i * 16);
            CP_COMMIT;
        }
        CP_WAIT0;
        __syncthreads();

        if (j0 <= i0 + r0 + 15) {
            float sacc[8][4];
            #pragma unroll
            for (int i = 0; i < 8; i++)
                #pragma unroll
                for (int j = 0; j < 4; j++) sacc[i][j] = 0.f;

            #pragma unroll
            for (int ks = 0; ks < 8; ks++) {
                const uint4 af = ldm4(qAddr + (ks * 8) * 4);
                #pragma unroll
                for (int p = 0; p < 4; p++) {
                    const uint4 bv = ldm4(kAddr + (p * 16 * FST + ks * 8) * 4);
                    mma8(sacc[2 * p],     af, bv.x, bv.z);
                    mma8(sacc[2 * p + 1], af, bv.y, bv.w);
                }
            }

            float mx0 = -1e30f, mx1 = -1e30f;
            #pragma unroll
            for (int nt = 0; nt < 8; nt++) {
                const int jc = j0 + nt * 8 + qd * 2;
                float v0 = sacc[nt][0] * 0.125f, v1 = sacc[nt][1] * 0.125f;
                float v2 = sacc[nt][2] * 0.125f, v3 = sacc[nt][3] * 0.125f;
                if (jc     > gr)     v0 = -1e30f;
                if (jc + 1 > gr)     v1 = -1e30f;
                if (jc     > gr + 8) v2 = -1e30f;
                if (jc + 1 > gr + 8) v3 = -1e30f;
                sacc[nt][0] = v0; sacc[nt][1] = v1; sacc[nt][2] = v2; sacc[nt][3] = v3;
                mx0 = fmaxf(mx0, fmaxf(v0, v1));
                mx1 = fmaxf(mx1, fmaxf(v2, v3));
            }
            mx0 = fmaxf(mx0, __shfl_xor_sync(0xffffffffu, mx0, 1));
            mx0 = fmaxf(mx0, __shfl_xor_sync(0xffffffffu, mx0, 2));
            mx1 = fmaxf(mx1, __shfl_xor_sync(0xffffffffu, mx1, 1));
            mx1 = fmaxf(mx1, __shfl_xor_sync(0xffffffffu, mx1, 2));
            const float mn0 = fmaxf(m0, mx0), mn1 = fmaxf(m1, mx1);
            const float es0 = expf(m0 - mn0), es1 = expf(m1 - mn1);
            m0 = mn0; m1 = mn1;

            float rs0 = 0.f, rs1 = 0.f;
            const int lr = r0 + grp;
            #pragma unroll
            for (int nt = 0; nt < 8; nt++) {
                const float p0 = expf(sacc[nt][0] - mn0);
                const float p1 = expf(sacc[nt][1] - mn0);
                const float p2 = expf(sacc[nt][2] - mn1);
                const float p3 = expf(sacc[nt][3] - mn1);
                rs0 += p0 + p1; rs1 += p2 + p3;
                *(float2*)(Ps + lr * FST + nt * 8 + qd * 2) =
                    make_float2(f2tff(p0), f2tff(p1));
                *(float2*)(Ps + (lr + 8) * FST + nt * 8 + qd * 2) =
                    make_float2(f2tff(p2), f2tff(p3));
            }
            rs0 += __shfl_xor_sync(0xffffffffu, rs0, 1);
            rs0 += __shfl_xor_sync(0xffffffffu, rs0, 2);
            rs1 += __shfl_xor_sync(0xffffffffu, rs1, 1);
            rs1 += __shfl_xor_sync(0xffffffffu, rs1, 2);
            l0 = l0 * es0 + rs0;
            l1 = l1 * es1 + rs1;

            #pragma unroll
            for (int nt = 0; nt < 8; nt++) {
                oacc[nt][0] *= es0; oacc[nt][1] *= es0;
                oacc[nt][2] *= es1; oacc[nt][3] *= es1;
            }
            __syncwarp();

            #pragma unroll
            for (int ks = 0; ks < 8; ks++) {
                const uint4 pf = ldm4(pAddr + (ks * 8) * 4);
                #pragma unroll
                for (int p = 0; p < 4; p++) {
                    const uint4 bv = ldm4(vAddr + (p * 16 * FST + ks * 8) * 4);
                    mma8(oacc[2 * p],     pf, bv.x, bv.z);
                    mma8(oacc[2 * p + 1], pf, bv.y, bv.w);
                }
            }
        }
    }

    const float inv0 = 1.f / l0, inv1 = 1.f / l1;
    #pragma unroll
    for (int nt = 0; nt < 8; nt++) {
        const int c = h * DH + nt * 8 + qd * 2;
        *(float2*)(o + (long)(b * NS + gr) * DM + c) =
            make_float2(f2tff(oacc[nt][0] * inv0), f2tff(oacc[nt][1] * inv0));
        *(float2*)(o + (long)(b * NS + gr + 8) * DM + c) =
            make_float2(f2tff(oacc[nt][2] * inv1), f2tff(oacc[nt][3] * inv1));
    }
}

// ---------------------------------------------------------------------------
__global__ void __launch_bounds__(256)
ln_kernel(const float* __restrict__ in, const float* __restrict__ g,
          const float* __restrict__ b, float* __restrict__ out,
          float* __restrict__ outr)
{
    const float* p = in + (long)blockIdx.x * DM;
    float* po  = out  + (long)blockIdx.x * DM;
    float* por = outr + (long)blockIdx.x * DM;
    const int tid = threadIdx.x;
    __shared__ float red[256];
    float vals[4];
    float s = 0.f;
    #pragma unroll
    for (int i = 0; i < 4; i++) { vals[i] = p[tid + i * 256]; s += vals[i]; }
    red[tid] = s; __syncthreads();
    for (int st = 128; st > 0; st >>= 1) {
        if (tid < st) red[tid] += red[tid + st];
        __syncthreads();
    }
    const float mean = red[0] * (1.f / DM); __syncthreads();
    float sq = 0.f;
    #pragma unroll
    for (int i = 0; i < 4; i++) { float d = vals[i] - mean; sq += d * d; }
    red[tid] = sq; __syncthreads();
    for (int st = 128; st > 0; st >>= 1) {
        if (tid < st) red[tid] += red[tid + st];
        __syncthreads();
    }
    const float sd = sqrtf(red[0] / (DM - 1));
    const float inv = 1.f / (sd + 1e-6f);
    #pragma unroll
    for (int i = 0; i < 4; i++) {
        const int d = tid + i * 256;
        const float r = g[d] * (vals[i] - mean) * inv + b[d];
        po[d] = r;
        por[d] = f2tff(r);
    }
}

__global__ void __launch_bounds__(256)
embed_kernel(const int* __restrict__ tokens, const float* __restrict__ emb,
             float* __restrict__ x, float* __restrict__ xr)
{
    const int t = blockIdx.x;
    const int s = t & (NS - 1);
    const float* e = emb + (long)tokens[t] * DM;
    float* xo  = x  + (long)t * DM;
    float* xro = xr + (long)t * DM;
    const float nlog = -9.210340371976184f / (float)DM;
    for (int d = threadIdx.x; d < DM; d += 256) {
        const float freq = expf((float)(d & ~1) * nlog);
        const float ang = (float)s * freq;
        const float r = e[d] * 32.0f + ((d & 1) ? cosf(ang) : sinf(ang));
        xo[d] = r;
        xro[d] = f2tff(r);
    }
}

// ---------------------------------------------------------------------------
extern "C" void kernel_launch(void* const* d_in, const int* in_sizes, int n_in,
                              void* d_out, int out_size)
{
    const int*   tokens = (const int*)  d_in[0];
    const float* emb    = (const float*)d_in[1];
    const float* Wq     = (const float*)d_in[2];
    const float* Wk     = (const float*)d_in[3];
    const float* Wv     = (const float*)d_in[4];
    const float* Wo     = (const float*)d_in[5];
    const float* bo     = (const float*)d_in[6];
    const float* ln1g   = (const float*)d_in[7];
    const float* ln1b   = (const float*)d_in[8];
    const float* W1     = (const float*)d_in[9];
    const float* b1     = (const float*)d_in[10];
    const float* W2     = (const float*)d_in[11];
    const float* b2     = (const float*)d_in[12];
    const float* ln2g   = (const float*)d_in[13];
    const float* ln2b   = (const float*)d_in[14];
    const float* Wout   = (const float*)d_in[15];
    const float* bout   = (const float*)d_in[16];
    float* out = (float*)d_out;

    float *x, *xr, *res, *qkv, *o, *ffn, *vt, *bt;
    cudaGetSymbolAddress((void**)&x,   g_x);
    cudaGetSymbolAddress((void**)&xr,  g_xr);
    cudaGetSymbolAddress((void**)&res, g_res);
    cudaGetSymbolAddress((void**)&qkv, g_qkv);
    cudaGetSymbolAddress((void**)&o,   g_o);
    cudaGetSymbolAddress((void**)&ffn, g_ffn);
    cudaGetSymbolAddress((void**)&vt,  g_vt);
    cudaGetSymbolAddress((void**)&bt,  g_bt);

    constexpr int SM128 = 4 * (128 * 20 + 128 * 20) * 4;
    cudaFuncSetAttribute(gemm_tc<128>, cudaFuncAttributeMaxDynamicSharedMemorySize, SM128);
    cudaFuncSetAttribute(flash_attn,   cudaFuncAttributeMaxDynamicSharedMemorySize, FA_SMEM);

    float* q = qkv;
    float* k = qkv + NT * DM;
    float* v = qkv + 2 * NT * DM;
    const long HW = (long)NH * DM * DH;

    embed_kernel<<<NT, 256>>>(tokens, emb, x, xr);

    for (int l = 0; l < NL; l++) {
        // QKV weights -> bt[(h*64+n)*DM + k] (rounded)
        tr32<<<dim3(DM / 32, DH / 32, NH), 256>>>(Wq + l * HW, bt,          DM, DH, DH, NH, 0, (long)DM * DH);
        tr32<<<dim3(DM / 32, DH / 32, NH), 256>>>(Wk + l * HW, bt + HW,     DM, DH, DH, NH, 0, (long)DM * DH);
        tr32<<<dim3(DM / 32, DH / 32, NH), 256>>>(Wv + l * HW, bt + 2 * HW, DM, DH, DH, NH, 0, (long)DM * DH);
        gemm_tc<128><<<dim3(NT / 128, DM / 128, 3), 256, SM128>>>(
            xr, bt, nullptr, nullptr, qkv, DM, DM, DM, DM, 3,
            0, 0, 0, HW, 0, (long)NT * DM, 16);

        // V^T per head (rounded)
        tr32<<<dim3(NS / 32, DH / 32, NB * NH), 256>>>(
            v, vt, NS, DH, DM, NH, (long)NS * DM, DH);

        // flash attention -> o (rounded)
        flash_attn<<<dim3(NS / 128, NB * NH), 256, FA_SMEM>>>(q, k, vt, o);

        // O projection + bias + residual (fp32 out)
        tr32<<<dim3(DM / 32, DM / 32, 1), 256>>>(Wo + (long)l * DM * DM, bt, DM, DM, DM, 1, 0, 0);
        gemm_tc<128><<<dim3(NT / 128, DM / 128), 256, SM128>>>(
            o, bt, bo + l * DM, x, res, DM, DM, DM, DM, 1,
            0, 0, 0, 0, 0, 0, 1 | 2);
        ln_kernel<<<NT, 256>>>(res, ln1g + l * DM, ln1b + l * DM, x, xr);

        // FFN
        tr32<<<dim3(DM / 32, DFF / 32, 1), 256>>>(W1 + (long)l * DM * DFF, bt, DM, DFF, DFF, 1, 0, 0);
        gemm_tc<128><<<dim3(NT / 128, DFF / 128), 256, SM128>>>(
            xr, bt, b1 + l * DFF, nullptr, ffn, DM, DM, DM, DFF, 1,
            0, 0, 0, 0, 0, 0, 1 | 4 | 16);
        tr32<<<dim3(DFF / 32, DM / 32, 1), 256>>>(W2 + (long)l * DFF * DM, bt, DFF, DM, DM, 1, 0, 0);
        gemm_tc<128><<<dim3(NT / 128, DM / 128), 256, SM128>>>(
            ffn, bt, b2 + l * DM, x, res, DFF, DFF, DFF, DM, 1,
            0, 0, 0, 0, 0, 0, 1 | 2);
        ln_kernel<<<NT, 256>>>(res, ln2g + l * DM, ln2b + l * DM, x, xr);
    }

    tr32<<<dim3(DM / 32, NV / 32, 1), 256>>>(Wout, bt, DM, NV, NV, 1, 0, 0);
    gemm_tc<128><<<dim3(NT / 128, NV / 128), 256, SM128>>>(
        xr, bt, bout, nullptr, out, DM, DM, DM, NV, 1,
        0, 0, 0, 0, 0, 0, 1);
}